// round 5
// baseline (speedup 1.0000x reference)
#include <cuda_runtime.h>
#include <cuda_bf16.h>
#include <cuda_fp16.h>
#include <cstdint>

// Problem constants (fixed by the dataset)
constexpr int U_N  = 50000;
constexpr int I_N  = 100000;
constexpr int N_N  = 150000;   // U + I
constexpr int D    = 64;
constexpr int B_N  = 8192;
constexpr int HID  = 128;

constexpr int NTOT  = N_N + 2 * U_N + 2 * I_N;   // 450000 CSR rows (5 graphs)
constexpr int NSCAN = NTOT + 1;
constexpr int E_TOT = 5000000;

// int scratch layout
constexpr int OFF_DEG  = 0;
constexpr int DEG_PAD  = 450008;
constexpr int OFF_CNT  = DEG_PAD;
constexpr int CNT_PAD  = 450008;
constexpr int OFF_DOUT = OFF_CNT + CNT_PAD;
constexpr int DOUT_LEN = 2 * U_N + 2 * I_N;      // 300000
constexpr int OFF_PART = OFF_DOUT + DOUT_LEN;
constexpr int OFF_TICK = OFF_PART + 256;
constexpr int INT_TOT  = OFF_TICK + 4;

// CSR row bases within the concatenated degree/scan vector
constexpr int RB_GCN = 0;
constexpr int RB_U1  = N_N;
constexpr int RB_U2  = N_N + U_N;
constexpr int RB_I1  = N_N + 2 * U_N;
constexpr int RB_I2  = N_N + 2 * U_N + I_N;

// attention tiling
constexpr int NTU   = (2 * U_N) / 16;            // 6250
constexpr int NTI   = (2 * I_N) / 16;            // 12500
constexpr int BLK_U = (NTU + 7) / 8;             // 782
constexpr int BLK_I = (NTI + 7) / 8;             // 1563
constexpr int GRID_ATTN = BLK_U + BLK_I;         // 2345

// ---------------------------------------------------------------------------
// Scratch (device globals: allocation-free)
// ---------------------------------------------------------------------------
__device__ __align__(256) __half g_ui16_a[N_N * D];   // fp16 gather ping
__device__ __align__(256) __half g_ui16_b[N_N * D];   // fp16 gather pong
__device__ __align__(256) float  g_ui32[N_N * D];     // fp32 final gcn output
__device__ __align__(256) __half g_hu16[U_N * D];
__device__ __align__(256) __half g_hi16[I_N * D];
__device__ __align__(256) float  g_zu[U_N * 2 * D];
__device__ __align__(256) float  g_zi[I_N * 2 * D];
__device__ __align__(256) float  g_wdst[NTOT];
__device__ __align__(256) float  g_wsrc[DOUT_LEN];
__device__ __align__(256) float  g_wsum[4];
__device__ __align__(256) float  g_beta[4];
__device__ __align__(256) int    g_int[INT_TOT];
__device__ __align__(256) int    g_S[NSCAN + 8];
__device__ __align__(256) int    g_csr[E_TOT];

// ---------------------------------------------------------------------------
// Helpers
// ---------------------------------------------------------------------------
__device__ __forceinline__ float tanh_fast(float x) {
    float y;
    asm("tanh.approx.f32 %0, %1;" : "=f"(y) : "f"(x));
    return y;
}
__device__ __forceinline__ uint32_t pack_bf16(float lo, float hi) {
    uint32_t r;
    asm("cvt.rn.bf16x2.f32 %0, %1, %2;" : "=r"(r) : "f"(hi), "f"(lo));
    return r;
}
__device__ __forceinline__ void mma16816(float c[4], const uint32_t a[4],
                                         uint32_t b0, uint32_t b1) {
    asm volatile(
        "mma.sync.aligned.m16n8k16.row.col.f32.bf16.bf16.f32 "
        "{%0,%1,%2,%3}, {%4,%5,%6,%7}, {%8,%9}, {%0,%1,%2,%3};"
        : "+f"(c[0]), "+f"(c[1]), "+f"(c[2]), "+f"(c[3])
        : "r"(a[0]), "r"(a[1]), "r"(a[2]), "r"(a[3]), "r"(b0), "r"(b1));
}

// ---------------------------------------------------------------------------
// Fused init: zero int scratch + copy features into ui16/hu16/hi16
// ---------------------------------------------------------------------------
__global__ void initzero_k(const float4* __restrict__ uf, const float4* __restrict__ itf) {
    int t = blockIdx.x * blockDim.x + threadIdx.x;
    if (t < INT_TOT / 4) ((int4*)g_int)[t] = make_int4(0, 0, 0, 0);
    if (t >= N_N * 16) return;
    float4 v;
    __half2* dst_h;
    int hidx;
    if (t < U_N * 16) {
        v = uf[t];
        dst_h = (__half2*)g_hu16; hidx = 2 * t;
    } else {
        v = itf[t - U_N * 16];
        dst_h = (__half2*)g_hi16; hidx = 2 * (t - U_N * 16);
    }
    __half2 h0 = __floats2half2_rn(v.x, v.y);
    __half2 h1 = __floats2half2_rn(v.z, v.w);
    ((__half2*)g_ui16_a)[2 * t]     = h0;
    ((__half2*)g_ui16_a)[2 * t + 1] = h1;
    dst_h[hidx]     = h0;
    dst_h[hidx + 1] = h1;
}

// ---------------------------------------------------------------------------
// Fused degree counting: 9 jobs, one grid
// ---------------------------------------------------------------------------
struct CntJobs {
    const int* ptr[9];
    int        dego[9];
    int        cum[10];
};

__global__ void cnt_all_k(CntJobs J) {
    int t = blockIdx.x * blockDim.x + threadIdx.x;
    if (t >= J.cum[9]) return;
    int j = 0;
    #pragma unroll
    for (int k = 1; k < 9; k++) j += (t >= J.cum[k]);
    atomicAdd(&g_int[J.dego[j] + J.ptr[j][t - J.cum[j]]], 1);
}

// --- 3-phase exclusive scan over NSCAN ints (chunk = 2048) ---
__global__ void scan1_k(int n) {
    const int* deg = g_int + OFF_DEG;
    __shared__ int warpsum[8];
    int base = blockIdx.x * 2048 + threadIdx.x * 8;
    int v[8];
    int s = 0;
    #pragma unroll
    for (int i = 0; i < 8; i++) {
        int x = (base + i < n) ? deg[base + i] : 0;
        v[i] = s; s += x;
    }
    int lane = threadIdx.x & 31, w = threadIdx.x >> 5;
    int ts = s;
    #pragma unroll
    for (int o = 1; o < 32; o <<= 1) {
        int y = __shfl_up_sync(0xffffffffu, ts, o);
        if (lane >= o) ts += y;
    }
    if (lane == 31) warpsum[w] = ts;
    __syncthreads();
    if (w == 0 && lane < 8) {
        int x = warpsum[lane];
        #pragma unroll
        for (int o = 1; o < 8; o <<= 1) {
            int y = __shfl_up_sync(0xffu, x, o);
            if (lane >= o) x += y;
        }
        warpsum[lane] = x;
    }
    __syncthreads();
    int prefix = (w > 0 ? warpsum[w - 1] : 0) + (ts - s);
    #pragma unroll
    for (int i = 0; i < 8; i++)
        if (base + i < n) g_S[base + i] = prefix + v[i];
    if (threadIdx.x == 0) g_int[OFF_PART + blockIdx.x] = warpsum[7];
}

__global__ void scan2_k(int np) {
    int* part = g_int + OFF_PART;
    __shared__ int sh[256];
    int t = threadIdx.x;
    int x = (t < np) ? part[t] : 0;
    sh[t] = x;
    __syncthreads();
    for (int o = 1; o < 256; o <<= 1) {
        int y = (t >= o) ? sh[t - o] : 0;
        __syncthreads();
        sh[t] += y;
        __syncthreads();
    }
    if (t < np) part[t] = sh[t] - x;  // exclusive
}

// scan finalize + normalization weights (fused)
__global__ void scan3w_k() {
    int t = blockIdx.x * blockDim.x + threadIdx.x;
    if (t < NSCAN) g_S[t] += g_int[OFF_PART + (t >> 11)];
    if (t < NTOT) {
        float d = (float)g_int[OFF_DEG + t];
        g_wdst[t] = (t < N_N) ? ((d > 0.f) ? rsqrtf(d) : 0.f)
                              : rsqrtf(fmaxf(d, 1.f));
    }
    if (t < DOUT_LEN) g_wsrc[t] = rsqrtf(fmaxf((float)g_int[OFF_DOUT + t], 1.f));
}

// ---------------------------------------------------------------------------
// Fused CSR fill: 5 jobs, one grid
// ---------------------------------------------------------------------------
struct FillJobs {
    const int* src[5];
    const int* dst[5];
    int        rb[5];
    int        cum[6];
};

__global__ void fill_all_k(FillJobs J) {
    int t = blockIdx.x * blockDim.x + threadIdx.x;
    if (t >= J.cum[5]) return;
    int j = 0;
    #pragma unroll
    for (int k = 1; k < 5; k++) j += (t >= J.cum[k]);
    int local = t - J.cum[j];
    int row = J.rb[j] + J.dst[j][local];
    int p = atomicAdd(&g_int[OFF_CNT + row], 1);
    g_csr[g_S[row] + p] = J.src[j][local];
}

// ---------------------------------------------------------------------------
// Fused pull: all 5 graphs, warp-per-row, fp16 gather / fp32 accumulate.
// Also resets wsum for the following attention kernel.
// ---------------------------------------------------------------------------
__global__ void pull_all_k(const __half2* __restrict__ ui_in16,
                           __half2* __restrict__ ui_out16,
                           float* __restrict__ ui_out32, int last) {
    if (blockIdx.x == 0 && threadIdx.x < 4) g_wsum[threadIdx.x] = 0.f;
    int r = (blockIdx.x * blockDim.x + threadIdx.x) >> 5;
    if (r >= NTOT) return;
    int lane = threadIdx.x & 31;

    const __half2* in;
    const float* ws;
    float* zout = nullptr;
    int zoff = 0, lr;
    bool gcn = r < RB_U1;
    if (gcn)            { in = ui_in16;            ws = g_wdst;                 lr = r; }
    else if (r < RB_U2) { in = (const __half2*)g_hu16; ws = g_wsrc;             zout = g_zu; zoff = 0;  lr = r - RB_U1; }
    else if (r < RB_I1) { in = (const __half2*)g_hu16; ws = g_wsrc + U_N;       zout = g_zu; zoff = 64; lr = r - RB_U2; }
    else if (r < RB_I2) { in = (const __half2*)g_hi16; ws = g_wsrc + 2 * U_N;   zout = g_zi; zoff = 0;  lr = r - RB_I1; }
    else                { in = (const __half2*)g_hi16; ws = g_wsrc + 2 * U_N + I_N; zout = g_zi; zoff = 64; lr = r - RB_I2; }

    int s = g_S[r], e = g_S[r + 1];
    float2 acc = make_float2(0.f, 0.f);
    int j = s;
    for (; j + 4 <= e; j += 4) {
        int c0 = g_csr[j], c1 = g_csr[j + 1], c2 = g_csr[j + 2], c3 = g_csr[j + 3];
        float w0 = ws[c0], w1 = ws[c1], w2 = ws[c2], w3 = ws[c3];
        float2 v0 = __half22float2(in[(size_t)c0 * 32 + lane]);
        float2 v1 = __half22float2(in[(size_t)c1 * 32 + lane]);
        float2 v2 = __half22float2(in[(size_t)c2 * 32 + lane]);
        float2 v3 = __half22float2(in[(size_t)c3 * 32 + lane]);
        acc.x = fmaf(w0, v0.x, acc.x); acc.y = fmaf(w0, v0.y, acc.y);
        acc.x = fmaf(w1, v1.x, acc.x); acc.y = fmaf(w1, v1.y, acc.y);
        acc.x = fmaf(w2, v2.x, acc.x); acc.y = fmaf(w2, v2.y, acc.y);
        acc.x = fmaf(w3, v3.x, acc.x); acc.y = fmaf(w3, v3.y, acc.y);
    }
    for (; j < e; j++) {
        int c = g_csr[j];
        float w = ws[c];
        float2 v = __half22float2(in[(size_t)c * 32 + lane]);
        acc.x = fmaf(w, v.x, acc.x); acc.y = fmaf(w, v.y, acc.y);
    }
    float wd = g_wdst[r];
    float2 o = make_float2(acc.x * wd, acc.y * wd);
    if (gcn) {
        if (last) *(float2*)(ui_out32 + (size_t)lr * D + lane * 2) = o;
        else      ui_out16[(size_t)lr * 32 + lane] = __floats2half2_rn(o.x, o.y);
    } else {
        *(float2*)(zout + (size_t)lr * 128 + zoff + lane * 2) = o;
    }
}

// ---------------------------------------------------------------------------
// Fused HAN attention (user + item) with tensor cores + last-block softmax.
// ---------------------------------------------------------------------------
constexpr int WT_STRIDE = 72;

__global__ void attn_all_k(const float* __restrict__ W1u, const float* __restrict__ b1u,
                           const float* __restrict__ w2u,
                           const float* __restrict__ W1i, const float* __restrict__ b1i,
                           const float* __restrict__ w2i) {
    bool isU = blockIdx.x < BLK_U;
    const float* z  = isU ? g_zu : g_zi;
    const float* W1 = isU ? W1u : W1i;
    const float* b1 = isU ? b1u : b1i;
    const float* w2 = isU ? w2u : w2i;
    int ntiles = isU ? NTU : NTI;
    int bid    = isU ? blockIdx.x : blockIdx.x - BLK_U;
    float* wsp = g_wsum + (isU ? 0 : 2);

    __shared__ __align__(16) __nv_bfloat16 Wt[HID * WT_STRIDE];
    __shared__ float b1s[HID];
    __shared__ float w2s[HID];
    __shared__ float r0s[256], r1s[256];

    for (int i = threadIdx.x; i < D * HID; i += blockDim.x) {
        int k = i >> 7, h = i & 127;
        Wt[h * WT_STRIDE + k] = __float2bfloat16(W1[i]);
    }
    if (threadIdx.x < HID) {
        b1s[threadIdx.x] = b1[threadIdx.x];
        w2s[threadIdx.x] = w2[threadIdx.x];
    }
    __syncthreads();

    int warp = threadIdx.x >> 5;
    int lane = threadIdx.x & 31;
    int g = lane >> 2;
    int tig = lane & 3;
    int tile = bid * 8 + warp;

    float acc0 = 0.f, acc1 = 0.f;

    if (tile < ntiles) {
        const float* zb = z + (size_t)tile * 16 * D;
        uint32_t A[4][4];
        #pragma unroll
        for (int kt = 0; kt < 4; kt++) {
            int k0 = kt * 16 + tig * 2;
            float2 v;
            v = *(const float2*)(zb + g * D + k0);            A[kt][0] = pack_bf16(v.x, v.y);
            v = *(const float2*)(zb + (g + 8) * D + k0);      A[kt][1] = pack_bf16(v.x, v.y);
            v = *(const float2*)(zb + g * D + k0 + 8);        A[kt][2] = pack_bf16(v.x, v.y);
            v = *(const float2*)(zb + (g + 8) * D + k0 + 8);  A[kt][3] = pack_bf16(v.x, v.y);
        }
        float s0 = 0.f, s1 = 0.f;
        #pragma unroll
        for (int nt = 0; nt < 16; nt++) {
            float c[4] = {0.f, 0.f, 0.f, 0.f};
            const __nv_bfloat16* wrow = Wt + (nt * 8 + g) * WT_STRIDE;
            #pragma unroll
            for (int kt = 0; kt < 4; kt++) {
                uint32_t bb0 = *(const uint32_t*)(wrow + kt * 16 + tig * 2);
                uint32_t bb1 = *(const uint32_t*)(wrow + kt * 16 + tig * 2 + 8);
                mma16816(c, A[kt], bb0, bb1);
            }
            int col0 = nt * 8 + tig * 2;
            float q0 = b1s[col0], q1 = b1s[col0 + 1];
            float p0 = w2s[col0], p1 = w2s[col0 + 1];
            s0 = fmaf(tanh_fast(c[0] + q0), p0, s0);
            s0 = fmaf(tanh_fast(c[1] + q1), p1, s0);
            s1 = fmaf(tanh_fast(c[2] + q0), p0, s1);
            s1 = fmaf(tanh_fast(c[3] + q1), p1, s1);
        }
        s0 += __shfl_xor_sync(0xffffffffu, s0, 1);
        s0 += __shfl_xor_sync(0xffffffffu, s0, 2);
        s1 += __shfl_xor_sync(0xffffffffu, s1, 1);
        s1 += __shfl_xor_sync(0xffffffffu, s1, 2);
        if (tig == 0) {
            float v = s0 + s1;
            if (g & 1) acc1 += v; else acc0 += v;
        }
    }

    r0s[threadIdx.x] = acc0;
    r1s[threadIdx.x] = acc1;
    __syncthreads();
    for (int s = blockDim.x >> 1; s > 0; s >>= 1) {
        if (threadIdx.x < s) {
            r0s[threadIdx.x] += r0s[threadIdx.x + s];
            r1s[threadIdx.x] += r1s[threadIdx.x + s];
        }
        __syncthreads();
    }
    if (threadIdx.x == 0) {
        atomicAdd(&wsp[0], r0s[0]);
        atomicAdd(&wsp[1], r1s[0]);
        __threadfence();
        int old = atomicAdd(&g_int[OFF_TICK], 1);
        if (old == GRID_ATTN - 1) {
            volatile float* vw = g_wsum;
            {
                float a = vw[0] * (1.0f / U_N);
                float b = vw[1] * (1.0f / U_N);
                float m = fmaxf(a, b);
                float e0 = expf(a - m), e1 = expf(b - m);
                float inv = 1.f / (e0 + e1);
                g_beta[0] = e0 * inv; g_beta[1] = e1 * inv;
            }
            {
                float a = vw[2] * (1.0f / I_N);
                float b = vw[3] * (1.0f / I_N);
                float m = fmaxf(a, b);
                float e0 = expf(a - m), e1 = expf(b - m);
                float inv = 1.f / (e0 + e1);
                g_beta[2] = e0 * inv; g_beta[3] = e1 * inv;
            }
            g_int[OFF_TICK] = 0;
        }
    }
}

// ---------------------------------------------------------------------------
// Fused combine (user + item): h16 = beta0*z0 + beta1*z1   (iteration 1 only)
// ---------------------------------------------------------------------------
__global__ void combine_all_k() {
    int t = blockIdx.x * blockDim.x + threadIdx.x;
    if (t >= (U_N + I_N) * 16) return;
    int node = t >> 4;
    int c = t & 15;
    const float4* z;
    __half2* h;
    float b0, b1;
    if (node < U_N) {
        z = (const float4*)g_zu; h = (__half2*)g_hu16;
        b0 = g_beta[0]; b1 = g_beta[1];
    } else {
        node -= U_N;
        z = (const float4*)g_zi; h = (__half2*)g_hi16;
        b0 = g_beta[2]; b1 = g_beta[3];
    }
    float4 z0 = z[node * 32 + c];
    float4 z1 = z[node * 32 + 16 + c];
    float rx = fmaf(b0, z0.x, b1 * z1.x);
    float ry = fmaf(b0, z0.y, b1 * z1.y);
    float rz = fmaf(b0, z0.z, b1 * z1.z);
    float rw = fmaf(b0, z0.w, b1 * z1.w);
    h[node * 32 + c * 2]     = __floats2half2_rn(rx, ry);
    h[node * 32 + c * 2 + 1] = __floats2half2_rn(rz, rw);
}

// ---------------------------------------------------------------------------
// Epilogue: iter-2 combine fused into the batched gathers (fp32 inputs)
// ---------------------------------------------------------------------------
__global__ void out_k(const int* __restrict__ uidx, const int* __restrict__ iidx,
                      const int* __restrict__ nidx, float* __restrict__ out) {
    int t = blockIdx.x * blockDim.x + threadIdx.x;
    if (t >= B_N * 16) return;
    int b = t >> 4;
    int c = t & 15;
    const float4* zu4 = (const float4*)g_zu;
    const float4* zi4 = (const float4*)g_zi;
    const float4* ui4 = (const float4*)g_ui32;
    float4* o4 = (float4*)out;
    float bU0 = g_beta[0], bU1 = g_beta[1], bI0 = g_beta[2], bI1 = g_beta[3];

    {
        int u = uidx[b];
        float4 z0 = zu4[u * 32 + c];
        float4 z1 = zu4[u * 32 + 16 + c];
        float4 g = ui4[u * 16 + c];
        float4 r;
        r.x = 0.5f * (fmaf(bU0, z0.x, bU1 * z1.x) + g.x);
        r.y = 0.5f * (fmaf(bU0, z0.y, bU1 * z1.y) + g.y);
        r.z = 0.5f * (fmaf(bU0, z0.z, bU1 * z1.z) + g.z);
        r.w = 0.5f * (fmaf(bU0, z0.w, bU1 * z1.w) + g.w);
        o4[t] = r;
    }
    {
        int it = iidx[b];
        float4 z0 = zi4[it * 32 + c];
        float4 z1 = zi4[it * 32 + 16 + c];
        float4 g = ui4[(U_N + it) * 16 + c];
        float4 r;
        r.x = 0.5f * (fmaf(bI0, z0.x, bI1 * z1.x) + g.x);
        r.y = 0.5f * (fmaf(bI0, z0.y, bI1 * z1.y) + g.y);
        r.z = 0.5f * (fmaf(bI0, z0.z, bI1 * z1.z) + g.z);
        r.w = 0.5f * (fmaf(bI0, z0.w, bI1 * z1.w) + g.w);
        o4[B_N * 16 + t] = r;
    }
    {
        int itn = iidx[nidx[b]];
        float4 z0 = zi4[itn * 32 + c];
        float4 z1 = zi4[itn * 32 + 16 + c];
        float4 g = ui4[(U_N + itn) * 16 + c];
        float4 r;
        r.x = 0.5f * (fmaf(bI0, z0.x, bI1 * z1.x) + g.x);
        r.y = 0.5f * (fmaf(bI0, z0.y, bI1 * z1.y) + g.y);
        r.z = 0.5f * (fmaf(bI0, z0.z, bI1 * z1.z) + g.z);
        r.w = 0.5f * (fmaf(bI0, z0.w, bI1 * z1.w) + g.w);
        o4[2 * B_N * 16 + t] = r;
    }
}

// ---------------------------------------------------------------------------
// Host
// ---------------------------------------------------------------------------
static inline int nblk(long long n) { return (int)((n + 255) / 256); }

extern "C" void kernel_launch(void* const* d_in, const int* in_sizes, int n_in,
                              void* d_out, int out_size) {
    const float* user_feat = (const float*)d_in[0];
    const float* item_feat = (const float*)d_in[1];
    const float* sa_u_W1   = (const float*)d_in[2];
    const float* sa_u_b1   = (const float*)d_in[3];
    const float* sa_u_w2   = (const float*)d_in[4];
    const float* sa_i_W1   = (const float*)d_in[5];
    const float* sa_i_b1   = (const float*)d_in[6];
    const float* sa_i_w2   = (const float*)d_in[7];
    const int*   ui_e      = (const int*)d_in[8];
    const int*   ue1       = (const int*)d_in[9];
    const int*   ue2       = (const int*)d_in[10];
    const int*   ie1       = (const int*)d_in[11];
    const int*   ie2       = (const int*)d_in[12];
    const int*   uidx      = (const int*)d_in[13];
    const int*   iidx      = (const int*)d_in[14];
    const int*   nidx      = (const int*)d_in[15];

    const int Eui = in_sizes[8]  / 2;   // 2,000,000
    const int Eu  = in_sizes[9]  / 2;   //   500,000
    const int Ei  = in_sizes[11] / 2;   // 1,000,000

    __half *ui16_a, *ui16_b;
    float* ui32;
    cudaGetSymbolAddress((void**)&ui16_a, g_ui16_a);
    cudaGetSymbolAddress((void**)&ui16_b, g_ui16_b);
    cudaGetSymbolAddress((void**)&ui32,   g_ui32);

    const int T = 256;

    // ---- fused zero + feature init ----
    initzero_k<<<nblk((long long)N_N * 16), T>>>((const float4*)user_feat,
                                                 (const float4*)item_feat);

    // ---- fused degree counting (9 jobs) ----
    CntJobs cj;
    const int* cp[9]  = {ui_e, ue1 + Eu, ue2 + Eu, ie1 + Ei, ie2 + Ei,
                         ue1, ue2, ie1, ie2};
    const int  ce[9]  = {Eui, Eu, Eu, Ei, Ei, Eu, Eu, Ei, Ei};
    const int  cd[9]  = {OFF_DEG + RB_GCN, OFF_DEG + RB_U1, OFF_DEG + RB_U2,
                         OFF_DEG + RB_I1, OFF_DEG + RB_I2,
                         OFF_DOUT + 0, OFF_DOUT + U_N,
                         OFF_DOUT + 2 * U_N, OFF_DOUT + 2 * U_N + I_N};
    int acc = 0;
    for (int k = 0; k < 9; k++) {
        cj.ptr[k] = cp[k]; cj.dego[k] = cd[k]; cj.cum[k] = acc; acc += ce[k];
    }
    cj.cum[9] = acc;
    cnt_all_k<<<nblk(acc), T>>>(cj);

    // ---- scan -> CSR row offsets; fused weights ----
    const int nchunks = (NSCAN + 2047) / 2048;  // 220
    scan1_k<<<nchunks, T>>>(NSCAN);
    scan2_k<<<1, 256>>>(nchunks);
    scan3w_k<<<nblk(NSCAN), T>>>();

    // ---- fused CSR fill (5 jobs) ----
    FillJobs fj;
    const int* fs[5] = {ui_e + Eui, ue1, ue2, ie1, ie2};
    const int* fd[5] = {ui_e, ue1 + Eu, ue2 + Eu, ie1 + Ei, ie2 + Ei};
    const int  fe[5] = {Eui, Eu, Eu, Ei, Ei};
    const int  fb[5] = {RB_GCN, RB_U1, RB_U2, RB_I1, RB_I2};
    acc = 0;
    for (int k = 0; k < 5; k++) {
        fj.src[k] = fs[k]; fj.dst[k] = fd[k]; fj.rb[k] = fb[k];
        fj.cum[k] = acc; acc += fe[k];
    }
    fj.cum[5] = acc;
    fill_all_k<<<nblk(acc), T>>>(fj);

    // ---- 2 propagation iterations ----
    // iter 0: gather ui16_a -> write ui16_b (fp16)
    pull_all_k<<<nblk((long long)NTOT * 32), T>>>((const __half2*)ui16_a,
                                                  (__half2*)ui16_b, nullptr, 0);
    attn_all_k<<<GRID_ATTN, 256>>>(sa_u_W1, sa_u_b1, sa_u_w2,
                                   sa_i_W1, sa_i_b1, sa_i_w2);
    combine_all_k<<<nblk((long long)(U_N + I_N) * 16), T>>>();

    // iter 1: gather ui16_b -> write ui32 (fp32, epilogue source)
    pull_all_k<<<nblk((long long)NTOT * 32), T>>>((const __half2*)ui16_b,
                                                  nullptr, ui32, 1);
    attn_all_k<<<GRID_ATTN, 256>>>(sa_u_W1, sa_u_b1, sa_u_w2,
                                   sa_i_W1, sa_i_b1, sa_i_w2);

    // ---- epilogue ----
    out_k<<<nblk((long long)B_N * 16), T>>>(uidx, iidx, nidx, (float*)d_out);
}

// round 6
// speedup vs baseline: 1.1348x; 1.1348x over previous
#include <cuda_runtime.h>
#include <cuda_bf16.h>
#include <cstdint>

// Problem constants (fixed by the dataset)
constexpr int U_N  = 50000;
constexpr int I_N  = 100000;
constexpr int N_N  = 150000;   // U + I
constexpr int D    = 64;
constexpr int B_N  = 8192;
constexpr int HID  = 128;

constexpr int NTOT  = N_N + 2 * U_N + 2 * I_N;   // 450000 CSR rows (5 graphs)
constexpr int NSCAN = NTOT + 1;
constexpr int E_TOT = 5000000;

// int scratch layout
constexpr int OFF_DEG  = 0;
constexpr int DEG_PAD  = 450008;
constexpr int OFF_CNT  = DEG_PAD;
constexpr int CNT_PAD  = 450008;
constexpr int OFF_DOUT = OFF_CNT + CNT_PAD;
constexpr int DOUT_LEN = 2 * U_N + 2 * I_N;      // 300000
constexpr int OFF_PART = OFF_DOUT + DOUT_LEN;
constexpr int INT_TOT  = OFF_PART + 256;

// CSR row bases within the concatenated degree/scan vector
constexpr int RB_GCN = 0;
constexpr int RB_U1  = N_N;
constexpr int RB_U2  = N_N + U_N;
constexpr int RB_I1  = N_N + 2 * U_N;
constexpr int RB_I2  = N_N + 2 * U_N + I_N;

// ---------------------------------------------------------------------------
// Scratch (device globals: allocation-free)
// ---------------------------------------------------------------------------
__device__ __align__(256) float g_ui_a[N_N * D];
__device__ __align__(256) float g_ui_b[N_N * D];
__device__ __align__(256) float g_hu[U_N * D];
__device__ __align__(256) float g_hi[I_N * D];
__device__ __align__(256) float g_zu[U_N * 2 * D];
__device__ __align__(256) float g_zi[I_N * 2 * D];
__device__ __align__(256) float g_wdst[NTOT];
__device__ __align__(256) float g_wsrc[DOUT_LEN];
__device__ __align__(256) float g_wsum[4];
__device__ __align__(256) float g_beta[4];
__device__ __align__(256) int   g_int[INT_TOT];
__device__ __align__(256) int   g_S[NSCAN + 8];
__device__ __align__(256) int   g_csr[E_TOT];

// ---------------------------------------------------------------------------
// Helpers
// ---------------------------------------------------------------------------
__device__ __forceinline__ float tanh_fast(float x) {
    float y;
    asm("tanh.approx.f32 %0, %1;" : "=f"(y) : "f"(x));
    return y;
}
__device__ __forceinline__ uint32_t pack_bf16(float lo, float hi) {
    uint32_t r;
    asm("cvt.rn.bf16x2.f32 %0, %1, %2;" : "=r"(r) : "f"(hi), "f"(lo));
    return r;
}
__device__ __forceinline__ void mma16816(float c[4], const uint32_t a[4],
                                         uint32_t b0, uint32_t b1) {
    asm volatile(
        "mma.sync.aligned.m16n8k16.row.col.f32.bf16.bf16.f32 "
        "{%0,%1,%2,%3}, {%4,%5,%6,%7}, {%8,%9}, {%0,%1,%2,%3};"
        : "+f"(c[0]), "+f"(c[1]), "+f"(c[2]), "+f"(c[3])
        : "r"(a[0]), "r"(a[1]), "r"(a[2]), "r"(a[3]), "r"(b0), "r"(b1));
}

// ---------------------------------------------------------------------------
// Kernels
// ---------------------------------------------------------------------------
__global__ void zero_i4_k(int4* p, int n4) {
    int t = blockIdx.x * blockDim.x + threadIdx.x;
    if (t < n4) p[t] = make_int4(0, 0, 0, 0);
}

__global__ void init_k(const float4* __restrict__ uf, const float4* __restrict__ itf,
                       float4* __restrict__ ui, float4* __restrict__ hu,
                       float4* __restrict__ hi) {
    int t = blockIdx.x * blockDim.x + threadIdx.x;
    if (t >= N_N * 16) return;
    if (t < U_N * 16) {
        float4 v = uf[t];
        ui[t] = v; hu[t] = v;
    } else {
        float4 v = itf[t - U_N * 16];
        ui[t] = v; hi[t - U_N * 16] = v;
    }
}

__global__ void cnt_k(const int* __restrict__ idx, int E, int* __restrict__ deg) {
    int t = blockIdx.x * blockDim.x + threadIdx.x;
    if (t < E) atomicAdd(&deg[idx[t]], 1);
}

// --- 3-phase exclusive scan over NSCAN ints (chunk = 2048) ---
__global__ void scan1_k(const int* __restrict__ deg, int n,
                        int* __restrict__ S, int* __restrict__ part) {
    __shared__ int warpsum[8];
    int base = blockIdx.x * 2048 + threadIdx.x * 8;
    int v[8];
    int s = 0;
    #pragma unroll
    for (int i = 0; i < 8; i++) {
        int x = (base + i < n) ? deg[base + i] : 0;
        v[i] = s; s += x;
    }
    int lane = threadIdx.x & 31, w = threadIdx.x >> 5;
    int ts = s;
    #pragma unroll
    for (int o = 1; o < 32; o <<= 1) {
        int y = __shfl_up_sync(0xffffffffu, ts, o);
        if (lane >= o) ts += y;
    }
    if (lane == 31) warpsum[w] = ts;
    __syncthreads();
    if (w == 0 && lane < 8) {
        int x = warpsum[lane];
        #pragma unroll
        for (int o = 1; o < 8; o <<= 1) {
            int y = __shfl_up_sync(0xffu, x, o);
            if (lane >= o) x += y;
        }
        warpsum[lane] = x;
    }
    __syncthreads();
    int prefix = (w > 0 ? warpsum[w - 1] : 0) + (ts - s);
    #pragma unroll
    for (int i = 0; i < 8; i++)
        if (base + i < n) S[base + i] = prefix + v[i];
    if (threadIdx.x == 0) part[blockIdx.x] = warpsum[7];
}

__global__ void scan2_k(int* part, int np) {
    __shared__ int sh[256];
    int t = threadIdx.x;
    int x = (t < np) ? part[t] : 0;
    sh[t] = x;
    __syncthreads();
    for (int o = 1; o < 256; o <<= 1) {
        int y = (t >= o) ? sh[t - o] : 0;
        __syncthreads();
        sh[t] += y;
        __syncthreads();
    }
    if (t < np) part[t] = sh[t] - x;  // exclusive
}

__global__ void scan3_k(int* __restrict__ S, const int* __restrict__ part, int n) {
    int t = blockIdx.x * blockDim.x + threadIdx.x;
    if (t < n) S[t] += part[t >> 11];
}

__global__ void weights_k(const int* __restrict__ din, const int* __restrict__ dout,
                          float* __restrict__ wdst, float* __restrict__ wsrc) {
    int t = blockIdx.x * blockDim.x + threadIdx.x;
    if (t < NTOT) {
        float d = (float)din[t];
        wdst[t] = (t < N_N) ? ((d > 0.f) ? rsqrtf(d) : 0.f)
                            : rsqrtf(fmaxf(d, 1.f));
    }
    if (t < DOUT_LEN) wsrc[t] = rsqrtf(fmaxf((float)dout[t], 1.f));
}

__global__ void fill_k(const int* __restrict__ src, const int* __restrict__ dst, int E,
                       const int* __restrict__ S, int row_base,
                       int* __restrict__ cnt, int* __restrict__ csr) {
    int e = blockIdx.x * blockDim.x + threadIdx.x;
    if (e >= E) return;
    int d = dst[e];
    int p = atomicAdd(&cnt[row_base + d], 1);
    csr[S[row_base + d] + p] = src[e];
}

// ---------------------------------------------------------------------------
// CSR pull SpMM: 2 rows per warp, 16 lanes/row, float4 payload.
// out[r] = wdst[r] * sum_c wsrc[c]*in[c]
// Doubles in-flight gathers per warp vs warp-per-row (latency-bound fix).
// ---------------------------------------------------------------------------
__global__ void pull_k(const int* __restrict__ S, const int* __restrict__ csr,
                       const float* __restrict__ wsrc, const float* __restrict__ wdst,
                       const float* __restrict__ in, float* __restrict__ out,
                       int nrows, int ostride, int ooff) {
    int r = (blockIdx.x * blockDim.x + threadIdx.x) >> 4;   // half-warp = row
    if (r >= nrows) return;
    int lane = threadIdx.x & 15;
    int s = S[r], e = S[r + 1];
    float4 acc = make_float4(0.f, 0.f, 0.f, 0.f);
    int j = s;
    for (; j + 4 <= e; j += 4) {
        int c0 = csr[j], c1 = csr[j + 1], c2 = csr[j + 2], c3 = csr[j + 3];
        float w0 = wsrc[c0], w1 = wsrc[c1], w2 = wsrc[c2], w3 = wsrc[c3];
        float4 v0 = *(const float4*)(in + (size_t)c0 * D + lane * 4);
        float4 v1 = *(const float4*)(in + (size_t)c1 * D + lane * 4);
        float4 v2 = *(const float4*)(in + (size_t)c2 * D + lane * 4);
        float4 v3 = *(const float4*)(in + (size_t)c3 * D + lane * 4);
        acc.x = fmaf(w0, v0.x, acc.x); acc.y = fmaf(w0, v0.y, acc.y);
        acc.z = fmaf(w0, v0.z, acc.z); acc.w = fmaf(w0, v0.w, acc.w);
        acc.x = fmaf(w1, v1.x, acc.x); acc.y = fmaf(w1, v1.y, acc.y);
        acc.z = fmaf(w1, v1.z, acc.z); acc.w = fmaf(w1, v1.w, acc.w);
        acc.x = fmaf(w2, v2.x, acc.x); acc.y = fmaf(w2, v2.y, acc.y);
        acc.z = fmaf(w2, v2.z, acc.z); acc.w = fmaf(w2, v2.w, acc.w);
        acc.x = fmaf(w3, v3.x, acc.x); acc.y = fmaf(w3, v3.y, acc.y);
        acc.z = fmaf(w3, v3.z, acc.z); acc.w = fmaf(w3, v3.w, acc.w);
    }
    for (; j < e; j++) {
        int c = csr[j];
        float w = wsrc[c];
        float4 v = *(const float4*)(in + (size_t)c * D + lane * 4);
        acc.x = fmaf(w, v.x, acc.x); acc.y = fmaf(w, v.y, acc.y);
        acc.z = fmaf(w, v.z, acc.z); acc.w = fmaf(w, v.w, acc.w);
    }
    float wd = wdst[r];
    float4 o = make_float4(acc.x * wd, acc.y * wd, acc.z * wd, acc.w * wd);
    *(float4*)(out + (size_t)r * ostride + ooff + lane * 4) = o;
}

// ---------------------------------------------------------------------------
// HAN attention via bf16 tensor-core GEMM (16-row tiles per warp).
// ---------------------------------------------------------------------------
constexpr int WT_STRIDE = 72;

__global__ void han_attn_k(const float* __restrict__ z, int n,
                           const float* __restrict__ W1, const float* __restrict__ b1,
                           const float* __restrict__ w2, float* __restrict__ wsum) {
    __shared__ __align__(16) __nv_bfloat16 Wt[HID * WT_STRIDE];
    __shared__ float b1s[HID];
    __shared__ float w2s[HID];
    __shared__ float r0s[256], r1s[256];

    for (int i = threadIdx.x; i < D * HID; i += blockDim.x) {
        int k = i >> 7, h = i & 127;
        Wt[h * WT_STRIDE + k] = __float2bfloat16(W1[i]);
    }
    if (threadIdx.x < HID) {
        b1s[threadIdx.x] = b1[threadIdx.x];
        w2s[threadIdx.x] = w2[threadIdx.x];
    }
    __syncthreads();

    int warp = threadIdx.x >> 5;
    int lane = threadIdx.x & 31;
    int g = lane >> 2;
    int tig = lane & 3;
    int ntiles = (2 * n) >> 4;

    float acc0 = 0.f, acc1 = 0.f;

    for (int tile = blockIdx.x * 8 + warp; tile < ntiles; tile += gridDim.x * 8) {
        const float* zb = z + (size_t)tile * 16 * D;
        uint32_t A[4][4];
        #pragma unroll
        for (int kt = 0; kt < 4; kt++) {
            int k0 = kt * 16 + tig * 2;
            float2 v;
            v = *(const float2*)(zb + g * D + k0);            A[kt][0] = pack_bf16(v.x, v.y);
            v = *(const float2*)(zb + (g + 8) * D + k0);      A[kt][1] = pack_bf16(v.x, v.y);
            v = *(const float2*)(zb + g * D + k0 + 8);        A[kt][2] = pack_bf16(v.x, v.y);
            v = *(const float2*)(zb + (g + 8) * D + k0 + 8);  A[kt][3] = pack_bf16(v.x, v.y);
        }
        float s0 = 0.f, s1 = 0.f;
        #pragma unroll
        for (int nt = 0; nt < 16; nt++) {
            float c[4] = {0.f, 0.f, 0.f, 0.f};
            const __nv_bfloat16* wrow = Wt + (nt * 8 + g) * WT_STRIDE;
            #pragma unroll
            for (int kt = 0; kt < 4; kt++) {
                uint32_t b0 = *(const uint32_t*)(wrow + kt * 16 + tig * 2);
                uint32_t b1v = *(const uint32_t*)(wrow + kt * 16 + tig * 2 + 8);
                mma16816(c, A[kt], b0, b1v);
            }
            int col0 = nt * 8 + tig * 2;
            float bb0 = b1s[col0], bb1 = b1s[col0 + 1];
            float ww0 = w2s[col0], ww1 = w2s[col0 + 1];
            s0 = fmaf(tanh_fast(c[0] + bb0), ww0, s0);
            s0 = fmaf(tanh_fast(c[1] + bb1), ww1, s0);
            s1 = fmaf(tanh_fast(c[2] + bb0), ww0, s1);
            s1 = fmaf(tanh_fast(c[3] + bb1), ww1, s1);
        }
        s0 += __shfl_xor_sync(0xffffffffu, s0, 1);
        s0 += __shfl_xor_sync(0xffffffffu, s0, 2);
        s1 += __shfl_xor_sync(0xffffffffu, s1, 1);
        s1 += __shfl_xor_sync(0xffffffffu, s1, 2);
        if (tig == 0) {
            float v = s0 + s1;
            if (g & 1) acc1 += v; else acc0 += v;
        }
    }

    r0s[threadIdx.x] = acc0;
    r1s[threadIdx.x] = acc1;
    __syncthreads();
    for (int s = blockDim.x >> 1; s > 0; s >>= 1) {
        if (threadIdx.x < s) {
            r0s[threadIdx.x] += r0s[threadIdx.x + s];
            r1s[threadIdx.x] += r1s[threadIdx.x + s];
        }
        __syncthreads();
    }
    if (threadIdx.x == 0) {
        atomicAdd(&wsum[0], r0s[0]);
        atomicAdd(&wsum[1], r1s[0]);
    }
}

__global__ void beta_k(const float* __restrict__ wsum, float inv_n, float* __restrict__ beta) {
    float a = wsum[0] * inv_n;
    float b = wsum[1] * inv_n;
    float m = fmaxf(a, b);
    float e0 = expf(a - m), e1 = expf(b - m);
    float inv = 1.f / (e0 + e1);
    beta[0] = e0 * inv;
    beta[1] = e1 * inv;
}

__global__ void zero_wsum_k(float* w) {
    if (threadIdx.x < 4) w[threadIdx.x] = 0.f;
}

// h[n,:] = beta0*z[n,0,:] + beta1*z[n,1,:]   (iteration 1 only)
__global__ void combine_k(const float* __restrict__ z, const float* __restrict__ beta,
                          float* __restrict__ h, int n) {
    int t = blockIdx.x * blockDim.x + threadIdx.x;
    if (t >= n * 16) return;
    int node = t >> 4;
    int c = t & 15;
    float b0 = beta[0], b1 = beta[1];
    float4 z0 = ((const float4*)z)[node * 32 + c];
    float4 z1 = ((const float4*)z)[node * 32 + 16 + c];
    float4 r;
    r.x = fmaf(b0, z0.x, b1 * z1.x);
    r.y = fmaf(b0, z0.y, b1 * z1.y);
    r.z = fmaf(b0, z0.z, b1 * z1.z);
    r.w = fmaf(b0, z0.w, b1 * z1.w);
    ((float4*)h)[t] = r;
}

// epilogue: iter-2 combine fused into the batched gathers
__global__ void out_k(const float* __restrict__ zu, const float* __restrict__ zi,
                      const float* __restrict__ ui, const float* __restrict__ beta,
                      const int* __restrict__ uidx, const int* __restrict__ iidx,
                      const int* __restrict__ nidx, float* __restrict__ out) {
    int t = blockIdx.x * blockDim.x + threadIdx.x;
    if (t >= B_N * 16) return;
    int b = t >> 4;
    int c = t & 15;
    const float4* zu4 = (const float4*)zu;
    const float4* zi4 = (const float4*)zi;
    const float4* ui4 = (const float4*)ui;
    float4* o4 = (float4*)out;
    float bU0 = beta[0], bU1 = beta[1], bI0 = beta[2], bI1 = beta[3];

    {
        int u = uidx[b];
        float4 z0 = zu4[u * 32 + c];
        float4 z1 = zu4[u * 32 + 16 + c];
        float4 g = ui4[u * 16 + c];
        float4 r;
        r.x = 0.5f * (fmaf(bU0, z0.x, bU1 * z1.x) + g.x);
        r.y = 0.5f * (fmaf(bU0, z0.y, bU1 * z1.y) + g.y);
        r.z = 0.5f * (fmaf(bU0, z0.z, bU1 * z1.z) + g.z);
        r.w = 0.5f * (fmaf(bU0, z0.w, bU1 * z1.w) + g.w);
        o4[t] = r;
    }
    {
        int it = iidx[b];
        float4 z0 = zi4[it * 32 + c];
        float4 z1 = zi4[it * 32 + 16 + c];
        float4 g = ui4[(U_N + it) * 16 + c];
        float4 r;
        r.x = 0.5f * (fmaf(bI0, z0.x, bI1 * z1.x) + g.x);
        r.y = 0.5f * (fmaf(bI0, z0.y, bI1 * z1.y) + g.y);
        r.z = 0.5f * (fmaf(bI0, z0.z, bI1 * z1.z) + g.z);
        r.w = 0.5f * (fmaf(bI0, z0.w, bI1 * z1.w) + g.w);
        o4[B_N * 16 + t] = r;
    }
    {
        int itn = iidx[nidx[b]];
        float4 z0 = zi4[itn * 32 + c];
        float4 z1 = zi4[itn * 32 + 16 + c];
        float4 g = ui4[(U_N + itn) * 16 + c];
        float4 r;
        r.x = 0.5f * (fmaf(bI0, z0.x, bI1 * z1.x) + g.x);
        r.y = 0.5f * (fmaf(bI0, z0.y, bI1 * z1.y) + g.y);
        r.z = 0.5f * (fmaf(bI0, z0.z, bI1 * z1.z) + g.z);
        r.w = 0.5f * (fmaf(bI0, z0.w, bI1 * z1.w) + g.w);
        o4[2 * B_N * 16 + t] = r;
    }
}

// ---------------------------------------------------------------------------
// Host
// ---------------------------------------------------------------------------
static inline int nblk(long long n) { return (int)((n + 255) / 256); }

extern "C" void kernel_launch(void* const* d_in, const int* in_sizes, int n_in,
                              void* d_out, int out_size) {
    const float* user_feat = (const float*)d_in[0];
    const float* item_feat = (const float*)d_in[1];
    const float* sa_u_W1   = (const float*)d_in[2];
    const float* sa_u_b1   = (const float*)d_in[3];
    const float* sa_u_w2   = (const float*)d_in[4];
    const float* sa_i_W1   = (const float*)d_in[5];
    const float* sa_i_b1   = (const float*)d_in[6];
    const float* sa_i_w2   = (const float*)d_in[7];
    const int*   ui_e      = (const int*)d_in[8];
    const int*   ue1       = (const int*)d_in[9];
    const int*   ue2       = (const int*)d_in[10];
    const int*   ie1       = (const int*)d_in[11];
    const int*   ie2       = (const int*)d_in[12];
    const int*   uidx      = (const int*)d_in[13];
    const int*   iidx      = (const int*)d_in[14];
    const int*   nidx      = (const int*)d_in[15];

    const int Eui = in_sizes[8]  / 2;   // 2,000,000
    const int Eu  = in_sizes[9]  / 2;   //   500,000
    const int Ei  = in_sizes[11] / 2;   // 1,000,000

    float *ui_a, *ui_b, *hu, *hi, *zu, *zi, *wdst, *wsrc, *wsum, *beta;
    int *ibuf, *S, *csr;
    cudaGetSymbolAddress((void**)&ui_a, g_ui_a);
    cudaGetSymbolAddress((void**)&ui_b, g_ui_b);
    cudaGetSymbolAddress((void**)&hu,   g_hu);
    cudaGetSymbolAddress((void**)&hi,   g_hi);
    cudaGetSymbolAddress((void**)&zu,   g_zu);
    cudaGetSymbolAddress((void**)&zi,   g_zi);
    cudaGetSymbolAddress((void**)&wdst, g_wdst);
    cudaGetSymbolAddress((void**)&wsrc, g_wsrc);
    cudaGetSymbolAddress((void**)&wsum, g_wsum);
    cudaGetSymbolAddress((void**)&beta, g_beta);
    cudaGetSymbolAddress((void**)&ibuf, g_int);
    cudaGetSymbolAddress((void**)&S,    g_S);
    cudaGetSymbolAddress((void**)&csr,  g_csr);

    int* deg  = ibuf + OFF_DEG;
    int* cnt  = ibuf + OFF_CNT;
    int* dout = ibuf + OFF_DOUT;
    int* part = ibuf + OFF_PART;

    const int T = 256;

    // ---- zero int scratch ----
    zero_i4_k<<<nblk(INT_TOT / 4), T>>>((int4*)ibuf, INT_TOT / 4);

    // ---- init features ----
    init_k<<<nblk((long long)N_N * 16), T>>>((const float4*)user_feat,
                                             (const float4*)item_feat,
                                             (float4*)ui_a, (float4*)hu, (float4*)hi);

    // ---- degree counts ----
    cnt_k<<<nblk(Eui), T>>>(ui_e,       Eui, deg + RB_GCN);
    cnt_k<<<nblk(Eu),  T>>>(ue1 + Eu,   Eu,  deg + RB_U1);
    cnt_k<<<nblk(Eu),  T>>>(ue2 + Eu,   Eu,  deg + RB_U2);
    cnt_k<<<nblk(Ei),  T>>>(ie1 + Ei,   Ei,  deg + RB_I1);
    cnt_k<<<nblk(Ei),  T>>>(ie2 + Ei,   Ei,  deg + RB_I2);
    cnt_k<<<nblk(Eu),  T>>>(ue1,        Eu,  dout + 0);
    cnt_k<<<nblk(Eu),  T>>>(ue2,        Eu,  dout + U_N);
    cnt_k<<<nblk(Ei),  T>>>(ie1,        Ei,  dout + 2 * U_N);
    cnt_k<<<nblk(Ei),  T>>>(ie2,        Ei,  dout + 2 * U_N + I_N);

    // ---- global exclusive scan -> CSR row offsets ----
    const int nchunks = (NSCAN + 2047) / 2048;  // 220
    scan1_k<<<nchunks, T>>>(deg, NSCAN, S, part);
    scan2_k<<<1, 256>>>(part, nchunks);
    scan3_k<<<nblk(NSCAN), T>>>(S, part, NSCAN);

    // ---- normalization weights ----
    weights_k<<<nblk(NTOT), T>>>(deg, dout, wdst, wsrc);

    // ---- CSR fill ----
    fill_k<<<nblk(Eui), T>>>(ui_e + Eui, ui_e,     Eui, S, RB_GCN, cnt, csr);
    fill_k<<<nblk(Eu),  T>>>(ue1,        ue1 + Eu, Eu,  S, RB_U1,  cnt, csr);
    fill_k<<<nblk(Eu),  T>>>(ue2,        ue2 + Eu, Eu,  S, RB_U2,  cnt, csr);
    fill_k<<<nblk(Ei),  T>>>(ie1,        ie1 + Ei, Ei,  S, RB_I1,  cnt, csr);
    fill_k<<<nblk(Ei),  T>>>(ie2,        ie2 + Ei, Ei,  S, RB_I2,  cnt, csr);

    // attention grids: 16-row tiles, 8 warps/block
    const int ntu = (2 * U_N) / 16, blk_u = (ntu + 7) / 8;
    const int nti = (2 * I_N) / 16, blk_i = (nti + 7) / 8;

    // ---- 2 propagation iterations ----
    const float* ui_in = ui_a;
    float* ui_out = ui_b;
    for (int iter = 0; iter < 2; ++iter) {
        pull_k<<<nblk((long long)N_N * 16), T>>>(S + RB_GCN, csr, wdst + RB_GCN,
                                                 wdst + RB_GCN, ui_in, ui_out,
                                                 N_N, 64, 0);
        pull_k<<<nblk((long long)U_N * 16), T>>>(S + RB_U1, csr, wsrc + 0,
                                                 wdst + RB_U1, hu, zu, U_N, 128, 0);
        pull_k<<<nblk((long long)U_N * 16), T>>>(S + RB_U2, csr, wsrc + U_N,
                                                 wdst + RB_U2, hu, zu, U_N, 128, 64);
        pull_k<<<nblk((long long)I_N * 16), T>>>(S + RB_I1, csr, wsrc + 2 * U_N,
                                                 wdst + RB_I1, hi, zi, I_N, 128, 0);
        pull_k<<<nblk((long long)I_N * 16), T>>>(S + RB_I2, csr, wsrc + 2 * U_N + I_N,
                                                 wdst + RB_I2, hi, zi, I_N, 128, 64);

        zero_wsum_k<<<1, 32>>>(wsum);
        han_attn_k<<<blk_u, 256>>>(zu, U_N, sa_u_W1, sa_u_b1, sa_u_w2, wsum + 0);
        beta_k<<<1, 1>>>(wsum + 0, 1.0f / U_N, beta + 0);
        han_attn_k<<<blk_i, 256>>>(zi, I_N, sa_i_W1, sa_i_b1, sa_i_w2, wsum + 2);
        beta_k<<<1, 1>>>(wsum + 2, 1.0f / I_N, beta + 2);

        if (iter == 0) {
            combine_k<<<nblk((long long)U_N * 16), T>>>(zu, beta + 0, hu, U_N);
            combine_k<<<nblk((long long)I_N * 16), T>>>(zi, beta + 2, hi, I_N);
        }

        const float* tmp = ui_in;
        ui_in = ui_out;
        ui_out = (float*)tmp;
    }

    // ---- epilogue ----
    out_k<<<nblk((long long)B_N * 16), T>>>(zu, zi, ui_in, beta,
                                            uidx, iidx, nidx, (float*)d_out);
}